// round 1
// baseline (speedup 1.0000x reference)
#include <cuda_runtime.h>
#include <cstdint>

#define NB 8
#define NSQ 128
#define NH 512
#define NE 512
#define NSTEPS 8
#define ROWS (NB*NSQ)   /* 1024 */
#define NW 2048         /* fused step-GEMM output columns */

// ---------------------------------------------------------------------------
// Scratch (device globals; no allocation allowed)
// ---------------------------------------------------------------------------
__device__ __align__(16) float g_x[ROWS*NE];
__device__ __align__(16) float g_ioux[ROWS*3*NH];
__device__ __align__(16) float g_ipre[ROWS*NH];
__device__ __align__(16) float g_o[ROWS*NH];
__device__ __align__(16) float g_u[ROWS*NH];
__device__ __align__(16) float g_fx[ROWS*NH];
__device__ __align__(16) float g_W[NE*NW];
__device__ __align__(16) float g_bstep[NW];
__device__ __align__(16) float g_G[ROWS*NW];
__device__ __align__(16) float g_h[2][ROWS*NH];
__device__ __align__(16) float g_c[2][ROWS*NH];
__device__ __align__(16) float g_iu[ROWS*NH];
__device__ __align__(16) float g_fc[ROWS*NH];
__device__ __align__(16) float g_cf[ROWS*NH];
__device__ __align__(16) float g_hf[ROWS*NH];
__device__ int g_rank[ROWS];
__device__ int g_maskv[ROWS];

// ---------------------------------------------------------------------------
// Packed f32x2 helpers (Blackwell FFMA2: 2x fp32 throughput, full precision)
// ---------------------------------------------------------------------------
__device__ __forceinline__ unsigned long long pack2(float lo, float hi) {
    unsigned long long r;
    asm("mov.b64 %0, {%1, %2};" : "=l"(r)
        : "r"(__float_as_uint(lo)), "r"(__float_as_uint(hi)));
    return r;
}
__device__ __forceinline__ unsigned long long dup2(float v) {
    unsigned long long r;
    unsigned u = __float_as_uint(v);
    asm("mov.b64 %0, {%1, %1};" : "=l"(r) : "r"(u));
    return r;
}
__device__ __forceinline__ void ffma2(unsigned long long& d,
                                      unsigned long long a,
                                      unsigned long long b) {
    asm("fma.rn.f32x2 %0, %1, %2, %0;" : "+l"(d) : "l"(a), "l"(b));
}
__device__ __forceinline__ float2 unpack2(unsigned long long v) {
    unsigned lo, hi;
    asm("mov.b64 {%0, %1}, %2;" : "=r"(lo), "=r"(hi) : "l"(v));
    return make_float2(__uint_as_float(lo), __uint_as_float(hi));
}

__device__ __forceinline__ float sigf(float x) {
    return 1.0f / (1.0f + __expf(-x));
}

// ---------------------------------------------------------------------------
// GEMM: C[M,N] = A[M,K] @ W[K,N] (+ bias). 64x64x16 tile, 256 thr, 4x4/thread
// ---------------------------------------------------------------------------
__global__ __launch_bounds__(256)
void gemm_f32(const float* __restrict__ A, const float* __restrict__ Wm,
              const float* __restrict__ bias, float* __restrict__ C,
              int M, int N, int K) {
    __shared__ __align__(16) float As[16][64];   // [k][m]
    __shared__ __align__(16) float Bs[16][64];   // [k][n]
    const int tid = threadIdx.x;
    const int tx = tid & 15, ty = tid >> 4;
    const int bm = blockIdx.y * 64, bn = blockIdx.x * 64;

    unsigned long long acc[4][2];
#pragma unroll
    for (int i = 0; i < 4; i++) { acc[i][0] = 0ULL; acc[i][1] = 0ULL; }

    const int arow = tid >> 2, akk = (tid & 3) << 2;
    const int bkk = tid >> 4, bnn = (tid & 15) << 2;

    for (int k0 = 0; k0 < K; k0 += 16) {
        float4 av = *(const float4*)(A + (size_t)(bm + arow) * K + k0 + akk);
        As[akk + 0][arow] = av.x;
        As[akk + 1][arow] = av.y;
        As[akk + 2][arow] = av.z;
        As[akk + 3][arow] = av.w;
        *(float4*)(&Bs[bkk][bnn]) =
            *(const float4*)(Wm + (size_t)(k0 + bkk) * N + bn + bnn);
        __syncthreads();
#pragma unroll
        for (int k = 0; k < 16; k++) {
            float4 a  = *(const float4*)(&As[k][ty << 2]);
            float4 bq = *(const float4*)(&Bs[k][tx << 2]);
            unsigned long long b01 = pack2(bq.x, bq.y);
            unsigned long long b23 = pack2(bq.z, bq.w);
            unsigned long long a0 = dup2(a.x), a1 = dup2(a.y);
            unsigned long long a2 = dup2(a.z), a3 = dup2(a.w);
            ffma2(acc[0][0], a0, b01); ffma2(acc[0][1], a0, b23);
            ffma2(acc[1][0], a1, b01); ffma2(acc[1][1], a1, b23);
            ffma2(acc[2][0], a2, b01); ffma2(acc[2][1], a2, b23);
            ffma2(acc[3][0], a3, b01); ffma2(acc[3][1], a3, b23);
        }
        __syncthreads();
    }

    float4 bv = make_float4(0.f, 0.f, 0.f, 0.f);
    if (bias) bv = *(const float4*)(bias + bn + (tx << 2));
#pragma unroll
    for (int i = 0; i < 4; i++) {
        float2 c01 = unpack2(acc[i][0]);
        float2 c23 = unpack2(acc[i][1]);
        float4 outv = make_float4(c01.x + bv.x, c01.y + bv.y,
                                  c23.x + bv.z, c23.y + bv.w);
        *(float4*)(C + (size_t)(bm + (ty << 2) + i) * N + bn + (tx << 2)) = outv;
    }
}

// ---------------------------------------------------------------------------
// Precompute kernels
// ---------------------------------------------------------------------------
__global__ void zero_hc() {
    int i = blockIdx.x * blockDim.x + threadIdx.x;
    if (i < ROWS * NH) { g_h[0][i] = 0.f; g_c[0][i] = 0.f; }
}

__global__ __launch_bounds__(128)
void embed_k(const int* __restrict__ ids, const float* __restrict__ emb) {
    int row = blockIdx.x, t = threadIdx.x;          // 128 float4 per row
    int tok = ids[row];
    ((float4*)g_x)[(size_t)row * 128 + t] =
        ((const float4*)emb)[(size_t)tok * 128 + t];
}

// split iou_x into i-preactivation / sigmoid(o) / tanh(u)
__global__ void act_split() {
    int idx = blockIdx.x * blockDim.x + threadIdx.x;
    if (idx >= ROWS * NH) return;
    int row = idx >> 9, j = idx & 511;
    const float* src = g_ioux + (size_t)row * 1536;
    g_ipre[idx] = src[j];
    g_o[idx]    = sigf(src[512 + j]);
    g_u[idx]    = tanhf(src[1024 + j]);
}

// Fuse step weights: [Wr(:, :H) | Wl(:, :H) | Wfh0+Wfh1 | Wfh2+Wfh3]
__global__ __launch_bounds__(512)
void prep_w(const float* __restrict__ Wr, const float* __restrict__ Wl,
            const float* __restrict__ f0, const float* __restrict__ f1,
            const float* __restrict__ f2, const float* __restrict__ f3,
            const float* __restrict__ br, const float* __restrict__ bl,
            const float* __restrict__ bf0, const float* __restrict__ bf1,
            const float* __restrict__ bf2, const float* __restrict__ bf3) {
    int k = blockIdx.x, j = threadIdx.x;
    g_W[(size_t)k * NW + j]        = Wr[(size_t)k * 1536 + j];
    g_W[(size_t)k * NW + 512 + j]  = Wl[(size_t)k * 1536 + j];
    g_W[(size_t)k * NW + 1024 + j] = f0[(size_t)k * 512 + j] + f1[(size_t)k * 512 + j];
    g_W[(size_t)k * NW + 1536 + j] = f2[(size_t)k * 512 + j] + f3[(size_t)k * 512 + j];
    if (k == 0) {
        g_bstep[j]        = br[j];
        g_bstep[512 + j]  = bl[j];
        g_bstep[1024 + j] = bf0[j] + bf1[j];
        g_bstep[1536 + j] = bf2[j] + bf3[j];
    }
}

// ---------------------------------------------------------------------------
// Per-step kernels (1 block per (b,n) row; 128 threads = float4 over H)
// G columns: [0,512)=Ar, [512,1024)=Al, [1024,1536)=Fr, [1536,2048)=Fl
// ---------------------------------------------------------------------------
__global__ __launch_bounds__(128)
void phase1(const int* __restrict__ tree, int step, int cur) {
    int blk = blockIdx.x;
    int b = blk >> 7, n = blk & 127;
    int t = threadIdx.x;
    __shared__ int s_ir[NSQ], s_il[NSQ];
    const int base = (b * NSTEPS + step) * 3;
    s_ir[t] = tree[(base + 1) * NSQ + t];
    s_il[t] = tree[(base + 2) * NSQ + t];
    __syncthreads();

    const float4* G4 = (const float4*)g_G;     // row stride 512 float4
    const int browbase = b * NSQ;
    float4 acc = make_float4(0.f, 0.f, 0.f, 0.f);
    // scatter-as-gather: sum Ar/Al rows whose idx_r/idx_l == n
    for (int sp = 0; sp < NSQ; sp++) {
        int rb = (browbase + sp) * 512;
        if (s_ir[sp] == n) {
            float4 v = G4[rb + t];
            acc.x += v.x; acc.y += v.y; acc.z += v.z; acc.w += v.w;
        }
        if (s_il[sp] == n) {
            float4 v = G4[rb + 128 + t];
            acc.x += v.x; acc.y += v.y; acc.z += v.z; acc.w += v.w;
        }
    }

    int row = browbase + n;
    float4 ip = ((const float4*)g_ipre)[(size_t)row * 128 + t];
    float4 uv = ((const float4*)g_u)[(size_t)row * 128 + t];
    float4 iu;
    iu.x = sigf(ip.x + acc.x) * uv.x;
    iu.y = sigf(ip.y + acc.y) * uv.y;
    iu.z = sigf(ip.z + acc.z) * uv.z;
    iu.w = sigf(ip.w + acc.w) * uv.w;
    ((float4*)g_iu)[(size_t)row * 128 + t] = iu;

    int dR = tree[(base + 0) * NSQ + n];
    int rR = s_ir[n], lR = s_il[n];
    float4 fx4 = ((const float4*)g_fx)[(size_t)(browbase + dR) * 128 + t];
    float4 fr4 = G4[(size_t)(browbase + rR) * 512 + 256 + t];
    float4 fl4 = G4[(size_t)(browbase + lR) * 512 + 384 + t];
    float4 cv  = ((const float4*)(g_c[cur]))[(size_t)row * 128 + t];
    float4 fc;
    fc.x = sigf(fx4.x + fr4.x + fl4.x) * cv.x;
    fc.y = sigf(fx4.y + fr4.y + fl4.y) * cv.y;
    fc.z = sigf(fx4.z + fr4.z + fl4.z) * cv.z;
    fc.w = sigf(fx4.w + fr4.w + fl4.w) * cv.w;
    ((float4*)g_fc)[(size_t)row * 128 + t] = fc;
}

__global__ __launch_bounds__(128)
void phase2(const int* __restrict__ tree, int step) {
    int blk = blockIdx.x;
    int b = blk >> 7, n = blk & 127;
    int t = threadIdx.x;
    __shared__ int s_id[NSQ];
    const int base = (b * NSTEPS + step) * 3;
    s_id[t] = tree[(base + 0) * NSQ + t];
    __syncthreads();

    const int browbase = b * NSQ;
    float4 acc = make_float4(0.f, 0.f, 0.f, 0.f);
    for (int sp = 0; sp < NSQ; sp++) {
        if (s_id[sp] == n) {
            float4 v = ((const float4*)g_fc)[(size_t)(browbase + sp) * 128 + t];
            acc.x += v.x; acc.y += v.y; acc.z += v.z; acc.w += v.w;
        }
    }
    int row = browbase + n;
    float4 iu = ((const float4*)g_iu)[(size_t)row * 128 + t];
    float4 cf = make_float4(iu.x + acc.x, iu.y + acc.y,
                            iu.z + acc.z, iu.w + acc.w);
    float4 ov = ((const float4*)g_o)[(size_t)row * 128 + t];
    float4 hf;
    hf.x = ov.x * tanhf(cf.x);
    hf.y = ov.y * tanhf(cf.y);
    hf.z = ov.z * tanhf(cf.z);
    hf.w = ov.w * tanhf(cf.w);
    ((float4*)g_cf)[(size_t)row * 128 + t] = cf;
    ((float4*)g_hf)[(size_t)row * 128 + t] = hf;
}

// exclusive prefix over global row mask (idx_d != 0), Hillis-Steele
__global__ __launch_bounds__(1024)
void rank_k(const int* __restrict__ tree, int step) {
    __shared__ int sh[ROWS];
    int p = threadIdx.x;
    int b = p >> 7, s = p & 127;
    int idxd = tree[((b * NSTEPS + step) * 3 + 0) * NSQ + s];
    int m = (idxd != 0) ? 1 : 0;
    g_maskv[p] = m;
    sh[p] = m;
    __syncthreads();
    for (int off = 1; off < ROWS; off <<= 1) {
        int add = (p >= off) ? sh[p - off] : 0;
        __syncthreads();
        sh[p] += add;
        __syncthreads();
    }
    g_rank[p] = sh[p] - m;   // exclusive rank
}

// masked_scatter compaction: k-th masked row <- full row k (global order)
__global__ __launch_bounds__(128)
void phase3(int cur) {
    int p = blockIdx.x, t = threadIdx.x;
    int nxt = cur ^ 1;
    if (g_maskv[p]) {
        int src = g_rank[p];
        ((float4*)(g_h[nxt]))[(size_t)p * 128 + t] =
            ((const float4*)g_hf)[(size_t)src * 128 + t];
        ((float4*)(g_c[nxt]))[(size_t)p * 128 + t] =
            ((const float4*)g_cf)[(size_t)src * 128 + t];
    } else {
        ((float4*)(g_h[nxt]))[(size_t)p * 128 + t] =
            ((const float4*)(g_h[cur]))[(size_t)p * 128 + t];
        ((float4*)(g_c[nxt]))[(size_t)p * 128 + t] =
            ((const float4*)(g_c[cur]))[(size_t)p * 128 + t];
    }
}

__global__ void copy_out(float* __restrict__ out, int cur) {
    int i = blockIdx.x * blockDim.x + threadIdx.x;
    if (i < ROWS * NH) out[i] = g_h[cur][i];
}

// ---------------------------------------------------------------------------
// Launch
// ---------------------------------------------------------------------------
extern "C" void kernel_launch(void* const* d_in, const int* in_sizes, int n_in,
                              void* d_out, int out_size) {
    const int*   ids      = (const int*)d_in[0];
    const int*   tree     = (const int*)d_in[1];
    const float* emb      = (const float*)d_in[2];
    const float* W_ioux   = (const float*)d_in[3];
    const float* W_iouh_r = (const float*)d_in[4];
    const float* b_iouh_r = (const float*)d_in[5];
    const float* W_iouh_l = (const float*)d_in[6];
    const float* b_iouh_l = (const float*)d_in[7];
    const float* W_fx     = (const float*)d_in[8];
    const float* W_fh0    = (const float*)d_in[9];
    const float* b_fh0    = (const float*)d_in[10];
    const float* W_fh1    = (const float*)d_in[11];
    const float* b_fh1    = (const float*)d_in[12];
    const float* W_fh2    = (const float*)d_in[13];
    const float* b_fh2    = (const float*)d_in[14];
    const float* W_fh3    = (const float*)d_in[15];
    const float* b_fh3    = (const float*)d_in[16];

    float *pX, *pIoux, *pFx, *pW, *pB, *pG, *pH;
    cudaGetSymbolAddress((void**)&pX,    g_x);
    cudaGetSymbolAddress((void**)&pIoux, g_ioux);
    cudaGetSymbolAddress((void**)&pFx,   g_fx);
    cudaGetSymbolAddress((void**)&pW,    g_W);
    cudaGetSymbolAddress((void**)&pB,    g_bstep);
    cudaGetSymbolAddress((void**)&pG,    g_G);
    cudaGetSymbolAddress((void**)&pH,    g_h);

    zero_hc<<<(ROWS * NH + 255) / 256, 256>>>();
    embed_k<<<ROWS, 128>>>(ids, emb);
    gemm_f32<<<dim3(1536 / 64, ROWS / 64), 256>>>(pX, W_ioux, nullptr, pIoux,
                                                  ROWS, 1536, NE);
    gemm_f32<<<dim3(512 / 64, ROWS / 64), 256>>>(pX, W_fx, nullptr, pFx,
                                                 ROWS, 512, NE);
    act_split<<<(ROWS * NH + 255) / 256, 256>>>();
    prep_w<<<512, 512>>>(W_iouh_r, W_iouh_l, W_fh0, W_fh1, W_fh2, W_fh3,
                         b_iouh_r, b_iouh_l, b_fh0, b_fh1, b_fh2, b_fh3);

    int cur = 0;
    for (int s = 0; s < NSTEPS; s++) {
        gemm_f32<<<dim3(NW / 64, ROWS / 64), 256>>>(
            pH + (size_t)cur * ROWS * NH, pW, pB, pG, ROWS, NW, NH);
        phase1<<<ROWS, 128>>>(tree, s, cur);
        phase2<<<ROWS, 128>>>(tree, s);
        rank_k<<<1, 1024>>>(tree, s);
        phase3<<<ROWS, 128>>>(cur);
        cur ^= 1;
    }
    copy_out<<<(ROWS * NH + 255) / 256, 256>>>((float*)d_out, cur);
}

// round 3
// speedup vs baseline: 2.3601x; 2.3601x over previous
#include <cuda_runtime.h>
#include <cstdint>

#define NB 8
#define NSQ 128
#define NH 512
#define NSTEPS 8
#define ROWS (NB*NSQ)   /* 1024 */
#define NW 2048

// mma.sync GEMM tiling: CTA 128x128, 4 warps (2x2) of 64x64, K-chunk 32
#define KC 32
#define NCH (NH/KC)             /* 16 */
#define A_SL (128*KC)           /* floats per A chunk */
#define B_SL (128*KC)
#define SMEM_DYN ((2*A_SL + 2*B_SL) * 4)   /* 64 KB */

// ---------------------------------------------------------------------------
// Scratch (device globals; no allocation allowed)
// ---------------------------------------------------------------------------
__device__ __align__(16) float g_x[ROWS*NH];      // tf32-rounded embeddings
__device__ __align__(16) float g_ipre[ROWS*NH];
__device__ __align__(16) float g_o[ROWS*NH];
__device__ __align__(16) float g_u[ROWS*NH];
__device__ __align__(16) float g_fx[ROWS*NH];
__device__ __align__(16) float g_Wt_pre[NW*NH];   // [Wioux | Wfx]^T, tf32-rounded
__device__ __align__(16) float g_Wt_step[NW*NH];  // [Wr1|Wl1|F01|F23]^T, rounded
__device__ __align__(16) float g_bstep[NW];
__device__ __align__(16) float g_G[ROWS*NW];
__device__ __align__(16) float g_h[2][ROWS*NH];   // exact h (carried)
__device__ __align__(16) float g_hr[ROWS*NH];     // tf32-rounded h (GEMM input)
__device__ __align__(16) float g_c[2][ROWS*NH];
__device__ __align__(16) float g_iu[ROWS*NH];
__device__ __align__(16) float g_fc[ROWS*NH];
__device__ __align__(16) float g_cf[ROWS*NH];
__device__ __align__(16) float g_hf[ROWS*NH];
__device__ int g_rank[ROWS];
__device__ int g_maskv[ROWS];

// ---------------------------------------------------------------------------
// Helpers
// ---------------------------------------------------------------------------
__device__ __forceinline__ uint32_t smem_u32(const void* p) {
    uint32_t a;
    asm("{ .reg .u64 t; cvta.to.shared.u64 t, %1; cvt.u32.u64 %0, t; }"
        : "=r"(a) : "l"(p));
    return a;
}
__device__ __forceinline__ void cp16(uint32_t s, const void* g) {
    asm volatile("cp.async.cg.shared.global [%0], [%1], 16;"
                 :: "r"(s), "l"(g) : "memory");
}
__device__ __forceinline__ void cp_commit() {
    asm volatile("cp.async.commit_group;" ::: "memory");
}
template <int N>
__device__ __forceinline__ void cp_wait() {
    asm volatile("cp.async.wait_group %0;" :: "n"(N) : "memory");
}
__device__ __forceinline__ float tf32r(float x) {
    uint32_t o;
    asm("cvt.rna.tf32.f32 %0, %1;" : "=r"(o) : "f"(x));
    return __uint_as_float(o);
}
__device__ __forceinline__ void mma1688(float* d, const uint32_t* a,
                                        uint32_t b0, uint32_t b1) {
    asm("mma.sync.aligned.m16n8k8.row.col.f32.tf32.tf32.f32 "
        "{%0,%1,%2,%3}, {%4,%5,%6,%7}, {%8,%9}, {%0,%1,%2,%3};"
        : "+f"(d[0]), "+f"(d[1]), "+f"(d[2]), "+f"(d[3])
        : "r"(a[0]), "r"(a[1]), "r"(a[2]), "r"(a[3]), "r"(b0), "r"(b1));
}
__device__ __forceinline__ float sigf(float x) {
    return 1.0f / (1.0f + __expf(-x));
}

// ---------------------------------------------------------------------------
// Tensor-core tf32 GEMM: C[1024,2048] = A[1024,512] @ Bt^T + bias
// A row-major [M,K]; Bt is [N,K] K-major. Inputs pre-rounded to tf32.
// SMEM rows are 128B (32 floats) with SW128 XOR swizzle on float4 blocks.
// ---------------------------------------------------------------------------
__global__ __launch_bounds__(128, 1)
void gemm_mma(const float* __restrict__ A, const float* __restrict__ Bt,
              const float* __restrict__ bias, float* __restrict__ C) {
    extern __shared__ float sm[];
    float* Abuf[2] = { sm, sm + A_SL };
    float* Bbuf[2] = { sm + 2 * A_SL, sm + 2 * A_SL + B_SL };

    const int tid  = threadIdx.x;
    const int wid  = tid >> 5, lane = tid & 31;
    const int lq   = lane >> 2, cq = lane & 3;
    const int mw   = wid >> 1, nw = wid & 1;          // 2x2 warp grid
    const int bm   = blockIdx.y * 128, bn = blockIdx.x * 128;

    // cp.async staging: 8 float4 per thread per operand per chunk
    auto issue = [&](int s, int buf) {
        float* da = Abuf[buf];
        float* db = Bbuf[buf];
#pragma unroll
        for (int i = 0; i < 8; i++) {
            int idx = tid + (i << 7);          // 0..1023
            int row = idx >> 3, c4 = idx & 7;
            const float* ga = A + (size_t)(bm + row) * NH + s * KC + (c4 << 2);
            cp16(smem_u32(da + row * 32 + ((c4 ^ (row & 7)) << 2)), ga);
            const float* gb = Bt + (size_t)(bn + row) * NH + s * KC + (c4 << 2);
            cp16(smem_u32(db + row * 32 + ((c4 ^ (row & 7)) << 2)), gb);
        }
        cp_commit();
    };

    float acc[4][8][4];
#pragma unroll
    for (int mt = 0; mt < 4; mt++)
#pragma unroll
        for (int nt = 0; nt < 8; nt++)
#pragma unroll
            for (int q = 0; q < 4; q++) acc[mt][nt][q] = 0.f;

    issue(0, 0);

    // per-thread fragment row constants
    int r0c[4], r1c[4], r0s[4], r1s[4];
#pragma unroll
    for (int mt = 0; mt < 4; mt++) {
        int r0 = mw * 64 + mt * 16 + lq, r1 = r0 + 8;
        r0c[mt] = r0 * 32 + cq; r0s[mt] = r0 & 7;
        r1c[mt] = r1 * 32 + cq; r1s[mt] = r1 & 7;
    }
    int nc[8], ns[8];
#pragma unroll
    for (int nt = 0; nt < 8; nt++) {
        int n = nw * 64 + nt * 8 + lq;
        nc[nt] = n * 32 + cq; ns[nt] = n & 7;
    }

    for (int s = 0; s < NCH; s++) {
        const int buf = s & 1;
        if (s + 1 < NCH) { issue(s + 1, buf ^ 1); cp_wait<1>(); }
        else             { cp_wait<0>(); }
        __syncthreads();

        const float* Ab = Abuf[buf];
        const float* Bb = Bbuf[buf];
#pragma unroll
        for (int k8 = 0; k8 < 4; k8++) {
            const int blk0 = k8 << 1, blk1 = blk0 + 1;
            uint32_t a[4][4];
#pragma unroll
            for (int mt = 0; mt < 4; mt++) {
                a[mt][0] = __float_as_uint(Ab[r0c[mt] + ((blk0 ^ r0s[mt]) << 2)]);
                a[mt][1] = __float_as_uint(Ab[r1c[mt] + ((blk0 ^ r1s[mt]) << 2)]);
                a[mt][2] = __float_as_uint(Ab[r0c[mt] + ((blk1 ^ r0s[mt]) << 2)]);
                a[mt][3] = __float_as_uint(Ab[r1c[mt] + ((blk1 ^ r1s[mt]) << 2)]);
            }
#pragma unroll
            for (int nt = 0; nt < 8; nt++) {
                uint32_t b0 = __float_as_uint(Bb[nc[nt] + ((blk0 ^ ns[nt]) << 2)]);
                uint32_t b1 = __float_as_uint(Bb[nc[nt] + ((blk1 ^ ns[nt]) << 2)]);
#pragma unroll
                for (int mt = 0; mt < 4; mt++)
                    mma1688(acc[mt][nt], a[mt], b0, b1);
            }
        }
        __syncthreads();
    }

    // epilogue: add bias, write float2 pairs
#pragma unroll
    for (int mt = 0; mt < 4; mt++) {
        int row0 = bm + mw * 64 + mt * 16 + lq;
#pragma unroll
        for (int nt = 0; nt < 8; nt++) {
            int col = bn + nw * 64 + nt * 8 + (cq << 1);
            float bx = 0.f, by = 0.f;
            if (bias) { bx = bias[col]; by = bias[col + 1]; }
            float2 v0 = make_float2(acc[mt][nt][0] + bx, acc[mt][nt][1] + by);
            float2 v1 = make_float2(acc[mt][nt][2] + bx, acc[mt][nt][3] + by);
            *(float2*)(C + (size_t)row0 * NW + col) = v0;
            *(float2*)(C + (size_t)(row0 + 8) * NW + col) = v1;
        }
    }
}

// ---------------------------------------------------------------------------
// One-time prep kernels
// ---------------------------------------------------------------------------
__global__ void zero_hc() {
    int i = blockIdx.x * blockDim.x + threadIdx.x;
    if (i < ROWS * NH) { g_h[0][i] = 0.f; g_c[0][i] = 0.f; g_hr[i] = 0.f; }
}

__global__ __launch_bounds__(128)
void embed_k(const int* __restrict__ ids, const float* __restrict__ emb) {
    int row = blockIdx.x, t = threadIdx.x;
    int tok = ids[row];
    float4 v = ((const float4*)emb)[(size_t)tok * 128 + t];
    v.x = tf32r(v.x); v.y = tf32r(v.y); v.z = tf32r(v.z); v.w = tf32r(v.w);
    ((float4*)g_x)[(size_t)row * 128 + t] = v;
}

// Tiled transpose + tf32 round: dst[n_off+n][k] = s1[k][c1+n] (+ s2[k][n])
__global__ __launch_bounds__(256)
void tr_k(float* __restrict__ dst, int n_off,
          const float* __restrict__ s1, int ld1, int c1,
          const float* __restrict__ s2) {
    __shared__ float tile[32][33];
    int k0 = blockIdx.x * 32, n0 = blockIdx.y * 32;
    int tx = threadIdx.x & 31, ty = threadIdx.x >> 5;
    for (int i = ty; i < 32; i += 8) {
        float v = s1[(size_t)(k0 + i) * ld1 + c1 + n0 + tx];
        if (s2) v += s2[(size_t)(k0 + i) * NH + n0 + tx];
        tile[i][tx] = tf32r(v);
    }
    __syncthreads();
    for (int i = ty; i < 32; i += 8) {
        dst[(size_t)(n_off + n0 + i) * NH + k0 + tx] = tile[tx][i];
    }
}

__global__ __launch_bounds__(512)
void prep_b(const float* __restrict__ br, const float* __restrict__ bl,
            const float* __restrict__ b0, const float* __restrict__ b1,
            const float* __restrict__ b2, const float* __restrict__ b3) {
    int j = threadIdx.x;
    g_bstep[j]        = br[j];
    g_bstep[512 + j]  = bl[j];
    g_bstep[1024 + j] = b0[j] + b1[j];
    g_bstep[1536 + j] = b2[j] + b3[j];
}

// split precompute GEMM output (g_G, 2048 cols): [i_pre | o | u | fx]
__global__ void act_split() {
    int idx = blockIdx.x * blockDim.x + threadIdx.x;
    if (idx >= ROWS * NH) return;
    int row = idx >> 9, j = idx & 511;
    const float* src = g_G + (size_t)row * NW;
    g_ipre[idx] = src[j];
    g_o[idx]    = sigf(src[512 + j]);
    g_u[idx]    = tanhf(src[1024 + j]);
    g_fx[idx]   = src[1536 + j];
}

// ---------------------------------------------------------------------------
// Per-step kernels. G columns: [0,512)=Ar, [512,1024)=Al, [1024,1536)=Fr,
// [1536,2048)=Fl. Block ROWS (the extra block) computes mask ranks.
// ---------------------------------------------------------------------------
__global__ __launch_bounds__(128)
void phase1(const int* __restrict__ tree, int step, int cur) {
    int blk = blockIdx.x;
    int t = threadIdx.x;

    if (blk == ROWS) {                 // rank block: global mask prefix scan
        __shared__ int tsum[128];
        int loc[8];
        int s = 0;
#pragma unroll
        for (int q = 0; q < 8; q++) {
            int p = t * 8 + q;
            int b = p >> 7, ss = p & 127;
            int idxd = tree[((b * NSTEPS + step) * 3) * NSQ + ss];
            int m = (idxd != 0) ? 1 : 0;
            g_maskv[p] = m;
            loc[q] = s;
            s += m;
        }
        tsum[t] = s;
        __syncthreads();
        for (int off = 1; off < 128; off <<= 1) {
            int add = (t >= off) ? tsum[t - off] : 0;
            __syncthreads();
            tsum[t] += add;
            __syncthreads();
        }
        int pre = tsum[t] - s;
#pragma unroll
        for (int q = 0; q < 8; q++) g_rank[t * 8 + q] = pre + loc[q];
        return;
    }

    int b = blk >> 7, n = blk & 127;
    __shared__ int s_ir[NSQ], s_il[NSQ];
    const int base = (b * NSTEPS + step) * 3;
    s_ir[t] = tree[(base + 1) * NSQ + t];
    s_il[t] = tree[(base + 2) * NSQ + t];
    __syncthreads();

    const float4* G4 = (const float4*)g_G;
    const int browbase = b * NSQ;
    float4 acc = make_float4(0.f, 0.f, 0.f, 0.f);
    for (int sp = 0; sp < NSQ; sp++) {
        int rb = (browbase + sp) * 512;
        if (s_ir[sp] == n) {
            float4 v = G4[rb + t];
            acc.x += v.x; acc.y += v.y; acc.z += v.z; acc.w += v.w;
        }
        if (s_il[sp] == n) {
            float4 v = G4[rb + 128 + t];
            acc.x += v.x; acc.y += v.y; acc.z += v.z; acc.w += v.w;
        }
    }

    int row = browbase + n;
    float4 ip = ((const float4*)g_ipre)[(size_t)row * 128 + t];
    float4 uv = ((const float4*)g_u)[(size_t)row * 128 + t];
    float4 iu;
    iu.x = sigf(ip.x + acc.x) * uv.x;
    iu.y = sigf(ip.y + acc.y) * uv.y;
    iu.z = sigf(ip.z + acc.z) * uv.z;
    iu.w = sigf(ip.w + acc.w) * uv.w;
    ((float4*)g_iu)[(size_t)row * 128 + t] = iu;

    int dR = tree[(base + 0) * NSQ + n];
    int rR = s_ir[n], lR = s_il[n];
    float4 fx4 = ((const float4*)g_fx)[(size_t)(browbase + dR) * 128 + t];
    float4 fr4 = G4[(size_t)(browbase + rR) * 512 + 256 + t];
    float4 fl4 = G4[(size_t)(browbase + lR) * 512 + 384 + t];
    float4 cv  = ((const float4*)(g_c[cur]))[(size_t)row * 128 + t];
    float4 fc;
    fc.x = sigf(fx4.x + fr4.x + fl4.x) * cv.x;
    fc.y = sigf(fx4.y + fr4.y + fl4.y) * cv.y;
    fc.z = sigf(fx4.z + fr4.z + fl4.z) * cv.z;
    fc.w = sigf(fx4.w + fr4.w + fl4.w) * cv.w;
    ((float4*)g_fc)[(size_t)row * 128 + t] = fc;
}

__global__ __launch_bounds__(128)
void phase2(const int* __restrict__ tree, int step) {
    int blk = blockIdx.x;
    int b = blk >> 7, n = blk & 127;
    int t = threadIdx.x;
    __shared__ int s_id[NSQ];
    const int base = (b * NSTEPS + step) * 3;
    s_id[t] = tree[(base + 0) * NSQ + t];
    __syncthreads();

    const int browbase = b * NSQ;
    float4 acc = make_float4(0.f, 0.f, 0.f, 0.f);
    for (int sp = 0; sp < NSQ; sp++) {
        if (s_id[sp] == n) {
            float4 v = ((const float4*)g_fc)[(size_t)(browbase + sp) * 128 + t];
            acc.x += v.x; acc.y += v.y; acc.z += v.z; acc.w += v.w;
        }
    }
    int row = browbase + n;
    float4 iu = ((const float4*)g_iu)[(size_t)row * 128 + t];
    float4 cf = make_float4(iu.x + acc.x, iu.y + acc.y,
                            iu.z + acc.z, iu.w + acc.w);
    float4 ov = ((const float4*)g_o)[(size_t)row * 128 + t];
    float4 hf;
    hf.x = ov.x * tanhf(cf.x);
    hf.y = ov.y * tanhf(cf.y);
    hf.z = ov.z * tanhf(cf.z);
    hf.w = ov.w * tanhf(cf.w);
    ((float4*)g_cf)[(size_t)row * 128 + t] = cf;
    ((float4*)g_hf)[(size_t)row * 128 + t] = hf;
}

// masked_scatter compaction: k-th masked row <- full row k (global order)
// writes exact h/c for carry; also tf32-rounded copy of h for next GEMM
__global__ __launch_bounds__(128)
void phase3(int cur, float* __restrict__ out) {
    int p = blockIdx.x, t = threadIdx.x;
    int nxt = cur ^ 1;
    float4 hv, cv;
    if (g_maskv[p]) {
        int src = g_rank[p];
        hv = ((const float4*)g_hf)[(size_t)src * 128 + t];
        cv = ((const float4*)g_cf)[(size_t)src * 128 + t];
    } else {
        hv = ((const float4*)(g_h[cur]))[(size_t)p * 128 + t];
        cv = ((const float4*)(g_c[cur]))[(size_t)p * 128 + t];
    }
    if (out) {
        ((float4*)out)[(size_t)p * 128 + t] = hv;
    } else {
        ((float4*)(g_h[nxt]))[(size_t)p * 128 + t] = hv;
        ((float4*)(g_c[nxt]))[(size_t)p * 128 + t] = cv;
        float4 hr;
        hr.x = tf32r(hv.x); hr.y = tf32r(hv.y);
        hr.z = tf32r(hv.z); hr.w = tf32r(hv.w);
        ((float4*)g_hr)[(size_t)p * 128 + t] = hr;
    }
}

// ---------------------------------------------------------------------------
// Launch
// ---------------------------------------------------------------------------
extern "C" void kernel_launch(void* const* d_in, const int* in_sizes, int n_in,
                              void* d_out, int out_size) {
    const int*   ids      = (const int*)d_in[0];
    const int*   tree     = (const int*)d_in[1];
    const float* emb      = (const float*)d_in[2];
    const float* W_ioux   = (const float*)d_in[3];
    const float* W_iouh_r = (const float*)d_in[4];
    const float* b_iouh_r = (const float*)d_in[5];
    const float* W_iouh_l = (const float*)d_in[6];
    const float* b_iouh_l = (const float*)d_in[7];
    const float* W_fx     = (const float*)d_in[8];
    const float* W_fh0    = (const float*)d_in[9];
    const float* b_fh0    = (const float*)d_in[10];
    const float* W_fh1    = (const float*)d_in[11];
    const float* b_fh1    = (const float*)d_in[12];
    const float* W_fh2    = (const float*)d_in[13];
    const float* b_fh2    = (const float*)d_in[14];
    const float* W_fh3    = (const float*)d_in[15];
    const float* b_fh3    = (const float*)d_in[16];

    cudaFuncSetAttribute(gemm_mma, cudaFuncAttributeMaxDynamicSharedMemorySize,
                         SMEM_DYN);

    float *pX, *pXr, *pWtPre, *pWtStep, *pB, *pG, *pH, *pHr;
    cudaGetSymbolAddress((void**)&pX,      g_x);
    cudaGetSymbolAddress((void**)&pWtPre,  g_Wt_pre);
    cudaGetSymbolAddress((void**)&pWtStep, g_Wt_step);
    cudaGetSymbolAddress((void**)&pB,      g_bstep);
    cudaGetSymbolAddress((void**)&pG,      g_G);
    cudaGetSymbolAddress((void**)&pH,      g_h);
    cudaGetSymbolAddress((void**)&pHr,     g_hr);
    (void)pH; (void)pXr;

    zero_hc<<<(ROWS * NH + 255) / 256, 256>>>();
    embed_k<<<ROWS, 128>>>(ids, emb);

    // transpose weights to [N, K] K-major with tf32 rounding (once per launch)
    tr_k<<<dim3(16, 48), 256>>>(pWtPre, 0,    W_ioux,   1536, 0, nullptr);
    tr_k<<<dim3(16, 16), 256>>>(pWtPre, 1536, W_fx,     512,  0, nullptr);
    tr_k<<<dim3(16, 16), 256>>>(pWtStep, 0,    W_iouh_r, 1536, 0, nullptr);
    tr_k<<<dim3(16, 16), 256>>>(pWtStep, 512,  W_iouh_l, 1536, 0, nullptr);
    tr_k<<<dim3(16, 16), 256>>>(pWtStep, 1024, W_fh0,    512,  0, W_fh1);
    tr_k<<<dim3(16, 16), 256>>>(pWtStep, 1536, W_fh2,    512,  0, W_fh3);
    prep_b<<<1, 512>>>(b_iouh_r, b_iouh_l, b_fh0, b_fh1, b_fh2, b_fh3);

    // precompute GEMM: [iou_x | fx_x] = x @ [W_ioux | W_fx]
    gemm_mma<<<dim3(NW / 128, ROWS / 128), 128, SMEM_DYN>>>(pX, pWtPre,
                                                            nullptr, pG);
    act_split<<<(ROWS * NH + 255) / 256, 256>>>();

    int cur = 0;
    for (int s = 0; s < NSTEPS; s++) {
        gemm_mma<<<dim3(NW / 128, ROWS / 128), 128, SMEM_DYN>>>(pHr, pWtStep,
                                                                pB, pG);
        phase1<<<ROWS + 1, 128>>>(tree, s, cur);
        phase2<<<ROWS, 128>>>(tree, s);
        phase3<<<ROWS, 128>>>(cur, (s == NSTEPS - 1) ? (float*)d_out : nullptr);
        cur ^= 1;
    }
}

// round 4
// speedup vs baseline: 2.4896x; 1.0549x over previous
#include <cuda_runtime.h>
#include <cstdint>

#define NB 8
#define NSQ 128
#define NH 512
#define NSTEPS 8
#define ROWS (NB*NSQ)   /* 1024 */
#define NW 2048

// mma.sync GEMM tiling: CTA 128x128, 8 warps (2x4) of 64x32, K-chunk 32
#define KC 32
#define NCH (NH/KC)             /* 16 */
#define A_SL (128*KC)
#define B_SL (128*KC)
#define SMEM_DYN ((2*A_SL + 2*B_SL) * 4)   /* 64 KB */

// ---------------------------------------------------------------------------
// Scratch (device globals; no allocation allowed)
// ---------------------------------------------------------------------------
__device__ __align__(16) float g_x[ROWS*NH];      // tf32-rounded embeddings
__device__ __align__(16) float g_ipre[ROWS*NH];
__device__ __align__(16) float g_o[ROWS*NH];
__device__ __align__(16) float g_u[ROWS*NH];
__device__ __align__(16) float g_fx[ROWS*NH];
__device__ __align__(16) float g_Wt_pre[NW*NH];   // [Wioux | Wfx]^T, rounded
__device__ __align__(16) float g_Wt_step[NW*NH];  // [Wr1|Wl1|F01|F23]^T, rounded
__device__ __align__(16) float g_bstep[NW];
__device__ __align__(16) float g_G[ROWS*NW];
__device__ __align__(16) float g_h[2][ROWS*NH];   // exact h (carried)
__device__ __align__(16) float g_hr[ROWS*NH];     // tf32-rounded h (GEMM input)
__device__ __align__(16) float g_c[2][ROWS*NH];
__device__ __align__(16) float g_iu[ROWS*NH];
__device__ __align__(16) float g_fc[ROWS*NH];
__device__ __align__(16) float g_cf[ROWS*NH];
__device__ __align__(16) float g_hf[ROWS*NH];
__device__ int g_rank[ROWS];
__device__ int g_maskv[ROWS];

// ---------------------------------------------------------------------------
// Helpers
// ---------------------------------------------------------------------------
__device__ __forceinline__ uint32_t smem_u32(const void* p) {
    uint32_t a;
    asm("{ .reg .u64 t; cvta.to.shared.u64 t, %1; cvt.u32.u64 %0, t; }"
        : "=r"(a) : "l"(p));
    return a;
}
__device__ __forceinline__ void cp16(uint32_t s, const void* g) {
    asm volatile("cp.async.cg.shared.global [%0], [%1], 16;"
                 :: "r"(s), "l"(g) : "memory");
}
__device__ __forceinline__ void cp_commit() {
    asm volatile("cp.async.commit_group;" ::: "memory");
}
template <int N>
__device__ __forceinline__ void cp_wait() {
    asm volatile("cp.async.wait_group %0;" :: "n"(N) : "memory");
}
__device__ __forceinline__ float tf32r(float x) {
    uint32_t o;
    asm("cvt.rna.tf32.f32 %0, %1;" : "=r"(o) : "f"(x));
    return __uint_as_float(o);
}
__device__ __forceinline__ void mma1688(float* d, const uint32_t* a,
                                        uint32_t b0, uint32_t b1) {
    asm("mma.sync.aligned.m16n8k8.row.col.f32.tf32.tf32.f32 "
        "{%0,%1,%2,%3}, {%4,%5,%6,%7}, {%8,%9}, {%0,%1,%2,%3};"
        : "+f"(d[0]), "+f"(d[1]), "+f"(d[2]), "+f"(d[3])
        : "r"(a[0]), "r"(a[1]), "r"(a[2]), "r"(a[3]), "r"(b0), "r"(b1));
}
__device__ __forceinline__ float sigf(float x) {
    return 1.0f / (1.0f + __expf(-x));
}

// ---------------------------------------------------------------------------
// Tensor-core tf32 GEMM: C[1024,2048] = A[1024,512] @ Bt^T (+bias)
// mode 0: C = acc + bias (step GEMM -> g_G)
// mode 1: activation-split epilogue (precompute GEMM -> ipre/o/u/fx)
// ---------------------------------------------------------------------------
__global__ __launch_bounds__(256, 1)
void gemm_mma(const float* __restrict__ A, const float* __restrict__ Bt,
              const float* __restrict__ bias, float* __restrict__ C,
              int mode) {
    extern __shared__ float sm[];
    float* Abuf[2] = { sm, sm + A_SL };
    float* Bbuf[2] = { sm + 2 * A_SL, sm + 2 * A_SL + B_SL };

    const int tid  = threadIdx.x;
    const int wid  = tid >> 5, lane = tid & 31;
    const int lq   = lane >> 2, cq = lane & 3;
    const int mw   = wid >> 2, nw = wid & 3;          // 2x4 warp grid
    const int bm   = blockIdx.y * 128, bn = blockIdx.x * 128;

    auto issue = [&](int s, int buf) {
        float* da = Abuf[buf];
        float* db = Bbuf[buf];
#pragma unroll
        for (int i = 0; i < 4; i++) {
            int idx = tid + (i << 8);
            int row = idx >> 3, c4 = idx & 7;
            cp16(smem_u32(da + row * 32 + ((c4 ^ (row & 7)) << 2)),
                 A + (size_t)(bm + row) * NH + s * KC + (c4 << 2));
            cp16(smem_u32(db + row * 32 + ((c4 ^ (row & 7)) << 2)),
                 Bt + (size_t)(bn + row) * NH + s * KC + (c4 << 2));
        }
        cp_commit();
    };

    float acc[4][4][4];
#pragma unroll
    for (int mt = 0; mt < 4; mt++)
#pragma unroll
        for (int nt = 0; nt < 4; nt++)
#pragma unroll
            for (int q = 0; q < 4; q++) acc[mt][nt][q] = 0.f;

    issue(0, 0);

    int r0c[4], r1c[4], r0s[4], r1s[4];
#pragma unroll
    for (int mt = 0; mt < 4; mt++) {
        int r0 = mw * 64 + mt * 16 + lq, r1 = r0 + 8;
        r0c[mt] = r0 * 32 + cq; r0s[mt] = r0 & 7;
        r1c[mt] = r1 * 32 + cq; r1s[mt] = r1 & 7;
    }
    int nc[4], ns[4];
#pragma unroll
    for (int nt = 0; nt < 4; nt++) {
        int n = nw * 32 + nt * 8 + lq;
        nc[nt] = n * 32 + cq; ns[nt] = n & 7;
    }

    for (int s = 0; s < NCH; s++) {
        const int buf = s & 1;
        if (s + 1 < NCH) { issue(s + 1, buf ^ 1); cp_wait<1>(); }
        else             { cp_wait<0>(); }
        __syncthreads();

        const float* Ab = Abuf[buf];
        const float* Bb = Bbuf[buf];
#pragma unroll
        for (int k8 = 0; k8 < 4; k8++) {
            const int blk0 = k8 << 1, blk1 = blk0 + 1;
            uint32_t a[4][4];
#pragma unroll
            for (int mt = 0; mt < 4; mt++) {
                a[mt][0] = __float_as_uint(Ab[r0c[mt] + ((blk0 ^ r0s[mt]) << 2)]);
                a[mt][1] = __float_as_uint(Ab[r1c[mt] + ((blk0 ^ r1s[mt]) << 2)]);
                a[mt][2] = __float_as_uint(Ab[r0c[mt] + ((blk1 ^ r0s[mt]) << 2)]);
                a[mt][3] = __float_as_uint(Ab[r1c[mt] + ((blk1 ^ r1s[mt]) << 2)]);
            }
            uint32_t b[4][2];
#pragma unroll
            for (int nt = 0; nt < 4; nt++) {
                b[nt][0] = __float_as_uint(Bb[nc[nt] + ((blk0 ^ ns[nt]) << 2)]);
                b[nt][1] = __float_as_uint(Bb[nc[nt] + ((blk1 ^ ns[nt]) << 2)]);
            }
#pragma unroll
            for (int nt = 0; nt < 4; nt++)
#pragma unroll
                for (int mt = 0; mt < 4; mt++)
                    mma1688(acc[mt][nt], a[mt], b[nt][0], b[nt][1]);
        }
        __syncthreads();
    }

    if (mode == 0) {
#pragma unroll
        for (int mt = 0; mt < 4; mt++) {
            int row0 = bm + mw * 64 + mt * 16 + lq;
#pragma unroll
            for (int nt = 0; nt < 4; nt++) {
                int col = bn + nw * 32 + nt * 8 + (cq << 1);
                float bx = bias[col], by = bias[col + 1];
                *(float2*)(C + (size_t)row0 * NW + col) =
                    make_float2(acc[mt][nt][0] + bx, acc[mt][nt][1] + by);
                *(float2*)(C + (size_t)(row0 + 8) * NW + col) =
                    make_float2(acc[mt][nt][2] + bx, acc[mt][nt][3] + by);
            }
        }
    } else {
        // precompute split: seg 0 raw->ipre, 1 sigf->o, 2 tanh->u, 3 raw->fx
        const int seg = bn >> 9;
        float* D = (seg == 0) ? g_ipre : (seg == 1) ? g_o
                 : (seg == 2) ? g_u : g_fx;
#pragma unroll
        for (int mt = 0; mt < 4; mt++) {
            int row0 = bm + mw * 64 + mt * 16 + lq;
#pragma unroll
            for (int nt = 0; nt < 4; nt++) {
                int lcol = (bn & 511) + nw * 32 + nt * 8 + (cq << 1);
                float v[4] = { acc[mt][nt][0], acc[mt][nt][1],
                               acc[mt][nt][2], acc[mt][nt][3] };
                if (seg == 1) {
#pragma unroll
                    for (int q = 0; q < 4; q++) v[q] = sigf(v[q]);
                } else if (seg == 2) {
#pragma unroll
                    for (int q = 0; q < 4; q++) v[q] = tanhf(v[q]);
                }
                *(float2*)(D + (size_t)row0 * NH + lcol) =
                    make_float2(v[0], v[1]);
                *(float2*)(D + (size_t)(row0 + 8) * NH + lcol) =
                    make_float2(v[2], v[3]);
            }
        }
    }
}

// ---------------------------------------------------------------------------
// Fused init: embed (+tf32 round), zero h0/c0, bias fuse
// ---------------------------------------------------------------------------
__global__ __launch_bounds__(128)
void init_k(const int* __restrict__ ids, const float* __restrict__ emb,
            const float* __restrict__ br, const float* __restrict__ bl,
            const float* __restrict__ b0, const float* __restrict__ b1,
            const float* __restrict__ b2, const float* __restrict__ b3) {
    int row = blockIdx.x, t = threadIdx.x;
    int tok = ids[row];
    float4 v = ((const float4*)emb)[(size_t)tok * 128 + t];
    v.x = tf32r(v.x); v.y = tf32r(v.y); v.z = tf32r(v.z); v.w = tf32r(v.w);
    ((float4*)g_x)[(size_t)row * 128 + t] = v;
    float4 z = make_float4(0.f, 0.f, 0.f, 0.f);
    ((float4*)(g_h[0]))[(size_t)row * 128 + t] = z;
    ((float4*)(g_c[0]))[(size_t)row * 128 + t] = z;
    if (row < 4) {
        int j = t * 4;
        const float* s1 = (row == 0) ? br : (row == 1) ? bl
                        : (row == 2) ? b0 : b2;
        const float* s2 = (row == 2) ? b1 : (row == 3) ? b3 : nullptr;
        float4 bv = *(const float4*)(s1 + j);
        if (s2) {
            float4 b2v = *(const float4*)(s2 + j);
            bv.x += b2v.x; bv.y += b2v.y; bv.z += b2v.z; bv.w += b2v.w;
        }
        *(float4*)(g_bstep + row * 512 + j) = bv;
    }
}

// ---------------------------------------------------------------------------
// Fused transposes: all 6 weight blocks, one launch. grid (16, 128)
// ---------------------------------------------------------------------------
__global__ __launch_bounds__(256)
void tr_all(const float* __restrict__ Wioux, const float* __restrict__ Wfx,
            const float* __restrict__ Wr, const float* __restrict__ Wl,
            const float* __restrict__ f0, const float* __restrict__ f1,
            const float* __restrict__ f2, const float* __restrict__ f3) {
    __shared__ float tile[32][33];
    int y = blockIdx.y;
    const float *s1, *s2 = nullptr;
    float* dst; int n_off, ld1, ny;
    if (y < 48)       { dst = g_Wt_pre;  n_off = 0;    s1 = Wioux; ld1 = 1536; ny = y; }
    else if (y < 64)  { dst = g_Wt_pre;  n_off = 1536; s1 = Wfx;   ld1 = 512;  ny = y - 48; }
    else if (y < 80)  { dst = g_Wt_step; n_off = 0;    s1 = Wr;    ld1 = 1536; ny = y - 64; }
    else if (y < 96)  { dst = g_Wt_step; n_off = 512;  s1 = Wl;    ld1 = 1536; ny = y - 80; }
    else if (y < 112) { dst = g_Wt_step; n_off = 1024; s1 = f0; s2 = f1; ld1 = 512; ny = y - 96; }
    else              { dst = g_Wt_step; n_off = 1536; s1 = f2; s2 = f3; ld1 = 512; ny = y - 112; }

    int k0 = blockIdx.x * 32, n0 = ny * 32;
    int tx = threadIdx.x & 31, ty = threadIdx.x >> 5;
    for (int i = ty; i < 32; i += 8) {
        float v = s1[(size_t)(k0 + i) * ld1 + n0 + tx];
        if (s2) v += s2[(size_t)(k0 + i) * NH + n0 + tx];
        tile[i][tx] = tf32r(v);
    }
    __syncthreads();
    for (int i = ty; i < 32; i += 8) {
        dst[(size_t)(n_off + n0 + i) * NH + k0 + tx] = tile[tx][i];
    }
}

// ---------------------------------------------------------------------------
// Per-step kernels. G cols: [0,512)=Ar, [512,1024)=Al, [1024,1536)=Fr,
// [1536,2048)=Fl. Extra block ROWS computes mask ranks.
// step0: G == bias broadcast (h=0), c == 0 -> fc == 0.
// ---------------------------------------------------------------------------
__global__ __launch_bounds__(128)
void phase1(const int* __restrict__ tree, int step, int cur, int step0) {
    int blk = blockIdx.x;
    int t = threadIdx.x;

    if (blk == ROWS) {                 // rank block
        __shared__ int tsum[128];
        int loc[8];
        int s = 0;
#pragma unroll
        for (int q = 0; q < 8; q++) {
            int p = t * 8 + q;
            int b = p >> 7, ss = p & 127;
            int idxd = tree[((b * NSTEPS + step) * 3) * NSQ + ss];
            int m = (idxd != 0) ? 1 : 0;
            g_maskv[p] = m;
            loc[q] = s;
            s += m;
        }
        tsum[t] = s;
        __syncthreads();
        for (int off = 1; off < 128; off <<= 1) {
            int add = (t >= off) ? tsum[t - off] : 0;
            __syncthreads();
            tsum[t] += add;
            __syncthreads();
        }
        int pre = tsum[t] - s;
#pragma unroll
        for (int q = 0; q < 8; q++) g_rank[t * 8 + q] = pre + loc[q];
        return;
    }

    int b = blk >> 7, n = blk & 127;
    __shared__ int s_ir[NSQ], s_il[NSQ];
    const int base = (b * NSTEPS + step) * 3;
    s_ir[t] = tree[(base + 1) * NSQ + t];
    s_il[t] = tree[(base + 2) * NSQ + t];
    __syncthreads();

    const int browbase = b * NSQ;
    const int row = browbase + n;
    float4 acc = make_float4(0.f, 0.f, 0.f, 0.f);

    if (step0) {
        int nr = 0, nl = 0;
        for (int sp = 0; sp < NSQ; sp++) {
            nr += (s_ir[sp] == n);
            nl += (s_il[sp] == n);
        }
        float4 bAr = ((const float4*)g_bstep)[t];
        float4 bAl = ((const float4*)g_bstep)[128 + t];
        float fr = (float)nr, fl = (float)nl;
        acc.x = fr * bAr.x + fl * bAl.x;
        acc.y = fr * bAr.y + fl * bAl.y;
        acc.z = fr * bAr.z + fl * bAl.z;
        acc.w = fr * bAr.w + fl * bAl.w;
    } else {
        const float4* G4 = (const float4*)g_G;
        for (int sp = 0; sp < NSQ; sp++) {
            int rb = (browbase + sp) * 512;
            if (s_ir[sp] == n) {
                float4 v = G4[rb + t];
                acc.x += v.x; acc.y += v.y; acc.z += v.z; acc.w += v.w;
            }
            if (s_il[sp] == n) {
                float4 v = G4[rb + 128 + t];
                acc.x += v.x; acc.y += v.y; acc.z += v.z; acc.w += v.w;
            }
        }
    }

    float4 ip = ((const float4*)g_ipre)[(size_t)row * 128 + t];
    float4 uv = ((const float4*)g_u)[(size_t)row * 128 + t];
    float4 iu;
    iu.x = sigf(ip.x + acc.x) * uv.x;
    iu.y = sigf(ip.y + acc.y) * uv.y;
    iu.z = sigf(ip.z + acc.z) * uv.z;
    iu.w = sigf(ip.w + acc.w) * uv.w;
    ((float4*)g_iu)[(size_t)row * 128 + t] = iu;

    if (!step0) {                      // c==0 at step0 -> fc==0, skip
        const float4* G4 = (const float4*)g_G;
        int dR = tree[(base + 0) * NSQ + n];
        int rR = s_ir[n], lR = s_il[n];
        float4 fx4 = ((const float4*)g_fx)[(size_t)(browbase + dR) * 128 + t];
        float4 fr4 = G4[(size_t)(browbase + rR) * 512 + 256 + t];
        float4 fl4 = G4[(size_t)(browbase + lR) * 512 + 384 + t];
        float4 cv  = ((const float4*)(g_c[cur]))[(size_t)row * 128 + t];
        float4 fc;
        fc.x = sigf(fx4.x + fr4.x + fl4.x) * cv.x;
        fc.y = sigf(fx4.y + fr4.y + fl4.y) * cv.y;
        fc.z = sigf(fx4.z + fr4.z + fl4.z) * cv.z;
        fc.w = sigf(fx4.w + fr4.w + fl4.w) * cv.w;
        ((float4*)g_fc)[(size_t)row * 128 + t] = fc;
    }
}

__global__ __launch_bounds__(128)
void phase2(const int* __restrict__ tree, int step, int step0) {
    int blk = blockIdx.x;
    int b = blk >> 7, n = blk & 127;
    int t = threadIdx.x;
    const int browbase = b * NSQ;
    const int row = browbase + n;

    float4 acc = make_float4(0.f, 0.f, 0.f, 0.f);
    if (!step0) {
        __shared__ int s_id[NSQ];
        const int base = (b * NSTEPS + step) * 3;
        s_id[t] = tree[(base + 0) * NSQ + t];
        __syncthreads();
        for (int sp = 0; sp < NSQ; sp++) {
            if (s_id[sp] == n) {
                float4 v = ((const float4*)g_fc)[(size_t)(browbase + sp) * 128 + t];
                acc.x += v.x; acc.y += v.y; acc.z += v.z; acc.w += v.w;
            }
        }
    }
    float4 iu = ((const float4*)g_iu)[(size_t)row * 128 + t];
    float4 cf = make_float4(iu.x + acc.x, iu.y + acc.y,
                            iu.z + acc.z, iu.w + acc.w);
    float4 ov = ((const float4*)g_o)[(size_t)row * 128 + t];
    float4 hf;
    hf.x = ov.x * tanhf(cf.x);
    hf.y = ov.y * tanhf(cf.y);
    hf.z = ov.z * tanhf(cf.z);
    hf.w = ov.w * tanhf(cf.w);
    ((float4*)g_cf)[(size_t)row * 128 + t] = cf;
    ((float4*)g_hf)[(size_t)row * 128 + t] = hf;
}

// masked_scatter compaction; writes exact h/c + tf32-rounded h for next GEMM
__global__ __launch_bounds__(128)
void phase3(int cur, float* __restrict__ out) {
    int p = blockIdx.x, t = threadIdx.x;
    int nxt = cur ^ 1;
    float4 hv, cv;
    if (g_maskv[p]) {
        int src = g_rank[p];
        hv = ((const float4*)g_hf)[(size_t)src * 128 + t];
        cv = ((const float4*)g_cf)[(size_t)src * 128 + t];
    } else {
        hv = ((const float4*)(g_h[cur]))[(size_t)p * 128 + t];
        cv = ((const float4*)(g_c[cur]))[(size_t)p * 128 + t];
    }
    if (out) {
        ((float4*)out)[(size_t)p * 128 + t] = hv;
    } else {
        ((float4*)(g_h[nxt]))[(size_t)p * 128 + t] = hv;
        ((float4*)(g_c[nxt]))[(size_t)p * 128 + t] = cv;
        float4 hr;
        hr.x = tf32r(hv.x); hr.y = tf32r(hv.y);
        hr.z = tf32r(hv.z); hr.w = tf32r(hv.w);
        ((float4*)g_hr)[(size_t)p * 128 + t] = hr;
    }
}

// ---------------------------------------------------------------------------
// Launch
// ---------------------------------------------------------------------------
extern "C" void kernel_launch(void* const* d_in, const int* in_sizes, int n_in,
                              void* d_out, int out_size) {
    const int*   ids      = (const int*)d_in[0];
    const int*   tree     = (const int*)d_in[1];
    const float* emb      = (const float*)d_in[2];
    const float* W_ioux   = (const float*)d_in[3];
    const float* W_iouh_r = (const float*)d_in[4];
    const float* b_iouh_r = (const float*)d_in[5];
    const float* W_iouh_l = (const float*)d_in[6];
    const float* b_iouh_l = (const float*)d_in[7];
    const float* W_fx     = (const float*)d_in[8];
    const float* W_fh0    = (const float*)d_in[9];
    const float* b_fh0    = (const float*)d_in[10];
    const float* W_fh1    = (const float*)d_in[11];
    const float* b_fh1    = (const float*)d_in[12];
    const float* W_fh2    = (const float*)d_in[13];
    const float* b_fh2    = (const float*)d_in[14];
    const float* W_fh3    = (const float*)d_in[15];
    const float* b_fh3    = (const float*)d_in[16];

    cudaFuncSetAttribute(gemm_mma, cudaFuncAttributeMaxDynamicSharedMemorySize,
                         SMEM_DYN);

    float *pX, *pWtPre, *pWtStep, *pB, *pG, *pHr;
    cudaGetSymbolAddress((void**)&pX,      g_x);
    cudaGetSymbolAddress((void**)&pWtPre,  g_Wt_pre);
    cudaGetSymbolAddress((void**)&pWtStep, g_Wt_step);
    cudaGetSymbolAddress((void**)&pB,      g_bstep);
    cudaGetSymbolAddress((void**)&pG,      g_G);
    cudaGetSymbolAddress((void**)&pHr,     g_hr);

    init_k<<<ROWS, 128>>>(ids, emb, b_iouh_r, b_iouh_l,
                          b_fh0, b_fh1, b_fh2, b_fh3);
    tr_all<<<dim3(16, 128), 256>>>(W_ioux, W_fx, W_iouh_r, W_iouh_l,
                                   W_fh0, W_fh1, W_fh2, W_fh3);

    // precompute GEMM with fused activation-split epilogue
    gemm_mma<<<dim3(NW / 128, ROWS / 128), 256, SMEM_DYN>>>(pX, pWtPre,
                                                            nullptr, pG, 1);

    // step 0: h=0 -> GEMM output == bias (handled analytically), c=0 -> fc=0
    phase1<<<ROWS + 1, 128>>>(tree, 0, 0, 1);
    phase2<<<ROWS, 128>>>(tree, 0, 1);
    phase3<<<ROWS, 128>>>(0, nullptr);

    int cur = 1;
    for (int s = 1; s < NSTEPS; s++) {
        gemm_mma<<<dim3(NW / 128, ROWS / 128), 256, SMEM_DYN>>>(
            pHr, pWtStep, pB, pG, 0);
        phase1<<<ROWS + 1, 128>>>(tree, s, cur, 0);
        phase2<<<ROWS, 128>>>(tree, s, 0);
        phase3<<<ROWS, 128>>>(cur, (s == NSTEPS - 1) ? (float*)d_out : nullptr);
        cur ^= 1;
    }
}

// round 5
// speedup vs baseline: 3.4083x; 1.3690x over previous
#include <cuda_runtime.h>
#include <cstdint>

#define NB 8
#define NSQ 128
#define NH 512
#define NSTEPS 8
#define ROWS (NB*NSQ)   /* 1024 */
#define NW 2048

#define KC 32
#define NCH (NH/KC)
#define A_SL (128*KC)
#define B_SL (128*KC)
#define SMEM_DYN ((2*A_SL + 2*B_SL) * 4)   /* 64 KB */

// ---------------------------------------------------------------------------
// Scratch (device globals)
// ---------------------------------------------------------------------------
__device__ __align__(16) float g_x[ROWS*NH];
__device__ __align__(16) float g_ipre[ROWS*NH];
__device__ __align__(16) float g_o[ROWS*NH];
__device__ __align__(16) float g_u[ROWS*NH];
__device__ __align__(16) float g_fx[ROWS*NH];
__device__ __align__(16) float g_Wt_pre[NW*NH];
__device__ __align__(16) float g_Wt_step[NW*NH];
__device__ __align__(16) float g_bstep[NW];
__device__ __align__(16) float g_G[ROWS*NW];
__device__ __align__(16) float g_h[ROWS*NH];      // exact h (single buffer)
__device__ __align__(16) float g_hr[ROWS*NH];     // tf32-rounded mirror of h
__device__ __align__(16) float g_c[ROWS*NH];      // single buffer
__device__ __align__(16) float g_iu[ROWS*NH];
__device__ __align__(16) float g_fc[ROWS*NH];
// precomputed index structure (all 8 steps)
__device__ int g_listIU[NSTEPS*NB*NSQ*256];       // sp | (seg<<8)
__device__ int g_cntIU[NSTEPS*NB*NSQ];
__device__ int g_listD[NSTEPS*NB*NSQ*128];
__device__ int g_cntD[NSTEPS*NB*NSQ];
__device__ int g_maskv[NSTEPS*ROWS];
__device__ int g_dest[NSTEPS*ROWS];               // dest[k] = pos of k-th masked row
__device__ int g_nmask[NSTEPS];

// ---------------------------------------------------------------------------
// Helpers
// ---------------------------------------------------------------------------
__device__ __forceinline__ uint32_t smem_u32(const void* p) {
    uint32_t a;
    asm("{ .reg .u64 t; cvta.to.shared.u64 t, %1; cvt.u32.u64 %0, t; }"
        : "=r"(a) : "l"(p));
    return a;
}
__device__ __forceinline__ void cp16(uint32_t s, const void* g) {
    asm volatile("cp.async.cg.shared.global [%0], [%1], 16;"
                 :: "r"(s), "l"(g) : "memory");
}
__device__ __forceinline__ void cp_commit() {
    asm volatile("cp.async.commit_group;" ::: "memory");
}
template <int N>
__device__ __forceinline__ void cp_wait() {
    asm volatile("cp.async.wait_group %0;" :: "n"(N) : "memory");
}
__device__ __forceinline__ float tf32r(float x) {
    uint32_t o;
    asm("cvt.rna.tf32.f32 %0, %1;" : "=r"(o) : "f"(x));
    return __uint_as_float(o);
}
__device__ __forceinline__ void mma1688(float* d, const uint32_t* a,
                                        uint32_t b0, uint32_t b1) {
    asm("mma.sync.aligned.m16n8k8.row.col.f32.tf32.tf32.f32 "
        "{%0,%1,%2,%3}, {%4,%5,%6,%7}, {%8,%9}, {%0,%1,%2,%3};"
        : "+f"(d[0]), "+f"(d[1]), "+f"(d[2]), "+f"(d[3])
        : "r"(a[0]), "r"(a[1]), "r"(a[2]), "r"(a[3]), "r"(b0), "r"(b1));
}
__device__ __forceinline__ float sigf(float x) {
    return 1.0f / (1.0f + __expf(-x));
}

// ---------------------------------------------------------------------------
// Tensor-core tf32 GEMM (same engine as R4; mode 1 = act-split epilogue)
// ---------------------------------------------------------------------------
__global__ __launch_bounds__(256, 1)
void gemm_mma(const float* __restrict__ A, const float* __restrict__ Bt,
              const float* __restrict__ bias, float* __restrict__ C,
              int mode) {
    extern __shared__ float sm[];
    float* Abuf[2] = { sm, sm + A_SL };
    float* Bbuf[2] = { sm + 2 * A_SL, sm + 2 * A_SL + B_SL };

    const int tid  = threadIdx.x;
    const int wid  = tid >> 5, lane = tid & 31;
    const int lq   = lane >> 2, cq = lane & 3;
    const int mw   = wid >> 2, nw = wid & 3;
    const int bm   = blockIdx.y * 128, bn = blockIdx.x * 128;

    auto issue = [&](int s, int buf) {
        float* da = Abuf[buf];
        float* db = Bbuf[buf];
#pragma unroll
        for (int i = 0; i < 4; i++) {
            int idx = tid + (i << 8);
            int row = idx >> 3, c4 = idx & 7;
            cp16(smem_u32(da + row * 32 + ((c4 ^ (row & 7)) << 2)),
                 A + (size_t)(bm + row) * NH + s * KC + (c4 << 2));
            cp16(smem_u32(db + row * 32 + ((c4 ^ (row & 7)) << 2)),
                 Bt + (size_t)(bn + row) * NH + s * KC + (c4 << 2));
        }
        cp_commit();
    };

    float acc[4][4][4];
#pragma unroll
    for (int mt = 0; mt < 4; mt++)
#pragma unroll
        for (int nt = 0; nt < 4; nt++)
#pragma unroll
            for (int q = 0; q < 4; q++) acc[mt][nt][q] = 0.f;

    issue(0, 0);

    int r0c[4], r1c[4], r0s[4], r1s[4];
#pragma unroll
    for (int mt = 0; mt < 4; mt++) {
        int r0 = mw * 64 + mt * 16 + lq, r1 = r0 + 8;
        r0c[mt] = r0 * 32 + cq; r0s[mt] = r0 & 7;
        r1c[mt] = r1 * 32 + cq; r1s[mt] = r1 & 7;
    }
    int nc[4], ns[4];
#pragma unroll
    for (int nt = 0; nt < 4; nt++) {
        int n = nw * 32 + nt * 8 + lq;
        nc[nt] = n * 32 + cq; ns[nt] = n & 7;
    }

    for (int s = 0; s < NCH; s++) {
        const int buf = s & 1;
        if (s + 1 < NCH) { issue(s + 1, buf ^ 1); cp_wait<1>(); }
        else             { cp_wait<0>(); }
        __syncthreads();

        const float* Ab = Abuf[buf];
        const float* Bb = Bbuf[buf];
#pragma unroll
        for (int k8 = 0; k8 < 4; k8++) {
            const int blk0 = k8 << 1, blk1 = blk0 + 1;
            uint32_t a[4][4];
#pragma unroll
            for (int mt = 0; mt < 4; mt++) {
                a[mt][0] = __float_as_uint(Ab[r0c[mt] + ((blk0 ^ r0s[mt]) << 2)]);
                a[mt][1] = __float_as_uint(Ab[r1c[mt] + ((blk0 ^ r1s[mt]) << 2)]);
                a[mt][2] = __float_as_uint(Ab[r0c[mt] + ((blk1 ^ r0s[mt]) << 2)]);
                a[mt][3] = __float_as_uint(Ab[r1c[mt] + ((blk1 ^ r1s[mt]) << 2)]);
            }
            uint32_t b[4][2];
#pragma unroll
            for (int nt = 0; nt < 4; nt++) {
                b[nt][0] = __float_as_uint(Bb[nc[nt] + ((blk0 ^ ns[nt]) << 2)]);
                b[nt][1] = __float_as_uint(Bb[nc[nt] + ((blk1 ^ ns[nt]) << 2)]);
            }
#pragma unroll
            for (int nt = 0; nt < 4; nt++)
#pragma unroll
                for (int mt = 0; mt < 4; mt++)
                    mma1688(acc[mt][nt], a[mt], b[nt][0], b[nt][1]);
        }
        __syncthreads();
    }

    if (mode == 0) {
#pragma unroll
        for (int mt = 0; mt < 4; mt++) {
            int row0 = bm + mw * 64 + mt * 16 + lq;
#pragma unroll
            for (int nt = 0; nt < 4; nt++) {
                int col = bn + nw * 32 + nt * 8 + (cq << 1);
                float bx = bias[col], by = bias[col + 1];
                *(float2*)(C + (size_t)row0 * NW + col) =
                    make_float2(acc[mt][nt][0] + bx, acc[mt][nt][1] + by);
                *(float2*)(C + (size_t)(row0 + 8) * NW + col) =
                    make_float2(acc[mt][nt][2] + bx, acc[mt][nt][3] + by);
            }
        }
    } else {
        const int seg = bn >> 9;
        float* D = (seg == 0) ? g_ipre : (seg == 1) ? g_o
                 : (seg == 2) ? g_u : g_fx;
#pragma unroll
        for (int mt = 0; mt < 4; mt++) {
            int row0 = bm + mw * 64 + mt * 16 + lq;
#pragma unroll
            for (int nt = 0; nt < 4; nt++) {
                int lcol = (bn & 511) + nw * 32 + nt * 8 + (cq << 1);
                float v[4] = { acc[mt][nt][0], acc[mt][nt][1],
                               acc[mt][nt][2], acc[mt][nt][3] };
                if (seg == 1) {
#pragma unroll
                    for (int q = 0; q < 4; q++) v[q] = sigf(v[q]);
                } else if (seg == 2) {
#pragma unroll
                    for (int q = 0; q < 4; q++) v[q] = tanhf(v[q]);
                }
                *(float2*)(D + (size_t)row0 * NH + lcol) =
                    make_float2(v[0], v[1]);
                *(float2*)(D + (size_t)(row0 + 8) * NH + lcol) =
                    make_float2(v[2], v[3]);
            }
        }
    }
}

// ---------------------------------------------------------------------------
// Fused init: embed (+tf32 round), zero h/c/hr, fuse biases
// ---------------------------------------------------------------------------
__global__ __launch_bounds__(128)
void init_k(const int* __restrict__ ids, const float* __restrict__ emb,
            const float* __restrict__ br, const float* __restrict__ bl,
            const float* __restrict__ b0, const float* __restrict__ b1,
            const float* __restrict__ b2, const float* __restrict__ b3) {
    int row = blockIdx.x, t = threadIdx.x;
    int tok = ids[row];
    float4 v = ((const float4*)emb)[(size_t)tok * 128 + t];
    v.x = tf32r(v.x); v.y = tf32r(v.y); v.z = tf32r(v.z); v.w = tf32r(v.w);
    ((float4*)g_x)[(size_t)row * 128 + t] = v;
    float4 z = make_float4(0.f, 0.f, 0.f, 0.f);
    ((float4*)g_h)[(size_t)row * 128 + t]  = z;
    ((float4*)g_c)[(size_t)row * 128 + t]  = z;
    ((float4*)g_hr)[(size_t)row * 128 + t] = z;
    if (row < 4) {
        int j = t * 4;
        const float* s1 = (row == 0) ? br : (row == 1) ? bl
                        : (row == 2) ? b0 : b2;
        const float* s2 = (row == 2) ? b1 : (row == 3) ? b3 : nullptr;
        float4 bv = *(const float4*)(s1 + j);
        if (s2) {
            float4 b2v = *(const float4*)(s2 + j);
            bv.x += b2v.x; bv.y += b2v.y; bv.z += b2v.z; bv.w += b2v.w;
        }
        *(float4*)(g_bstep + row * 512 + j) = bv;
    }
}

// ---------------------------------------------------------------------------
// Fused weight transposes (as R4)
// ---------------------------------------------------------------------------
__global__ __launch_bounds__(256)
void tr_all(const float* __restrict__ Wioux, const float* __restrict__ Wfx,
            const float* __restrict__ Wr, const float* __restrict__ Wl,
            const float* __restrict__ f0, const float* __restrict__ f1,
            const float* __restrict__ f2, const float* __restrict__ f3) {
    __shared__ float tile[32][33];
    int y = blockIdx.y;
    const float *s1, *s2 = nullptr;
    float* dst; int n_off, ld1, ny;
    if (y < 48)       { dst = g_Wt_pre;  n_off = 0;    s1 = Wioux; ld1 = 1536; ny = y; }
    else if (y < 64)  { dst = g_Wt_pre;  n_off = 1536; s1 = Wfx;   ld1 = 512;  ny = y - 48; }
    else if (y < 80)  { dst = g_Wt_step; n_off = 0;    s1 = Wr;    ld1 = 1536; ny = y - 64; }
    else if (y < 96)  { dst = g_Wt_step; n_off = 512;  s1 = Wl;    ld1 = 1536; ny = y - 80; }
    else if (y < 112) { dst = g_Wt_step; n_off = 1024; s1 = f0; s2 = f1; ld1 = 512; ny = y - 96; }
    else              { dst = g_Wt_step; n_off = 1536; s1 = f2; s2 = f3; ld1 = 512; ny = y - 112; }

    int k0 = blockIdx.x * 32, n0 = ny * 32;
    int tx = threadIdx.x & 31, ty = threadIdx.x >> 5;
    for (int i = ty; i < 32; i += 8) {
        float v = s1[(size_t)(k0 + i) * ld1 + n0 + tx];
        if (s2) v += s2[(size_t)(k0 + i) * NH + n0 + tx];
        tile[i][tx] = tf32r(v);
    }
    __syncthreads();
    for (int i = ty; i < 32; i += 8) {
        dst[(size_t)(n_off + n0 + i) * NH + k0 + tx] = tile[tx][i];
    }
}

// ---------------------------------------------------------------------------
// Precompute scatter source lists for all steps (deterministic serial scan)
// grid = 64 (step*8+batch), 128 threads (one per destination n)
// ---------------------------------------------------------------------------
__global__ __launch_bounds__(128)
void lists_k(const int* __restrict__ tree) {
    int sb = blockIdx.x;
    int s = sb >> 3, b = sb & 7;
    __shared__ int s_id[NSQ], s_ir[NSQ], s_il[NSQ];
    int t = threadIdx.x;
    int base = (b * NSTEPS + s) * 3;
    s_id[t] = tree[(base + 0) * NSQ + t];
    s_ir[t] = tree[(base + 1) * NSQ + t];
    s_il[t] = tree[(base + 2) * NSQ + t];
    __syncthreads();

    int n = t;
    int* lIU = g_listIU + ((size_t)sb * 128 + n) * 256;
    int c = 0;
    for (int sp = 0; sp < NSQ; sp++) if (s_ir[sp] == n) lIU[c++] = sp;
    for (int sp = 0; sp < NSQ; sp++) if (s_il[sp] == n) lIU[c++] = sp | 256;
    g_cntIU[sb * 128 + n] = c;

    int* lD = g_listD + ((size_t)sb * 128 + n) * 128;
    int cd = 0;
    for (int sp = 0; sp < NSQ; sp++) if (s_id[sp] == n) lD[cd++] = sp;
    g_cntD[sb * 128 + n] = cd;
}

// per-step global mask rank + inverse map. grid = NSTEPS, 1024 threads
__global__ __launch_bounds__(1024)
void ranks_k(const int* __restrict__ tree) {
    int s = blockIdx.x;
    __shared__ int sh[ROWS];
    int p = threadIdx.x;
    int b = p >> 7, ss = p & 127;
    int idxd = tree[((b * NSTEPS + s) * 3) * NSQ + ss];
    int m = (idxd != 0) ? 1 : 0;
    g_maskv[s * ROWS + p] = m;
    sh[p] = m;
    __syncthreads();
    for (int off = 1; off < ROWS; off <<= 1) {
        int add = (p >= off) ? sh[p - off] : 0;
        __syncthreads();
        sh[p] += add;
        __syncthreads();
    }
    int rank = sh[p] - m;
    if (m) g_dest[s * ROWS + rank] = p;
    if (p == ROWS - 1) g_nmask[s] = sh[ROWS - 1];
}

// ---------------------------------------------------------------------------
// phase1: i-gate via precomputed gather lists; f-gate + fc
// ---------------------------------------------------------------------------
__global__ __launch_bounds__(128)
void phase1(const int* __restrict__ tree, int step, int step0) {
    int blk = blockIdx.x;
    int b = blk >> 7, n = blk & 127;
    int t = threadIdx.x;
    const int browbase = b * NSQ;
    const int row = browbase + n;
    const int sb = step * 8 + b;

    const int cnt = g_cntIU[sb * 128 + n];
    const int* lst = g_listIU + ((size_t)sb * 128 + n) * 256;
    float4 acc = make_float4(0.f, 0.f, 0.f, 0.f);

    if (step0) {
        int nr = 0;
        for (int k = 0; k < cnt; k++) nr += (lst[k] < 256);
        int nl = cnt - nr;
        float4 bAr = ((const float4*)g_bstep)[t];
        float4 bAl = ((const float4*)g_bstep)[128 + t];
        float fr = (float)nr, fl = (float)nl;
        acc.x = fr * bAr.x + fl * bAl.x;
        acc.y = fr * bAr.y + fl * bAl.y;
        acc.z = fr * bAr.z + fl * bAl.z;
        acc.w = fr * bAr.w + fl * bAl.w;
    } else {
        const float4* G4 = (const float4*)g_G;
        for (int k = 0; k < cnt; k++) {
            int e = lst[k];
            int sp = e & 255, seg = e >> 8;
            float4 v = G4[(size_t)(browbase + sp) * 512 + seg * 128 + t];
            acc.x += v.x; acc.y += v.y; acc.z += v.z; acc.w += v.w;
        }
    }

    float4 ip = ((const float4*)g_ipre)[(size_t)row * 128 + t];
    float4 uv = ((const float4*)g_u)[(size_t)row * 128 + t];
    float4 iu;
    iu.x = sigf(ip.x + acc.x) * uv.x;
    iu.y = sigf(ip.y + acc.y) * uv.y;
    iu.z = sigf(ip.z + acc.z) * uv.z;
    iu.w = sigf(ip.w + acc.w) * uv.w;
    ((float4*)g_iu)[(size_t)row * 128 + t] = iu;

    if (!step0) {
        const float4* G4 = (const float4*)g_G;
        const int base = (b * NSTEPS + step) * 3;
        int dR = tree[(base + 0) * NSQ + n];
        int rR = tree[(base + 1) * NSQ + n];
        int lR = tree[(base + 2) * NSQ + n];
        float4 fx4 = ((const float4*)g_fx)[(size_t)(browbase + dR) * 128 + t];
        float4 fr4 = G4[(size_t)(browbase + rR) * 512 + 256 + t];
        float4 fl4 = G4[(size_t)(browbase + lR) * 512 + 384 + t];
        float4 cv  = ((const float4*)g_c)[(size_t)row * 128 + t];
        float4 fc;
        fc.x = sigf(fx4.x + fr4.x + fl4.x) * cv.x;
        fc.y = sigf(fx4.y + fr4.y + fl4.y) * cv.y;
        fc.z = sigf(fx4.z + fr4.z + fl4.z) * cv.z;
        fc.w = sigf(fx4.w + fr4.w + fl4.w) * cv.w;
        ((float4*)g_fc)[(size_t)row * 128 + t] = fc;
    }
}

// ---------------------------------------------------------------------------
// phase23: cf/hf + direct inverted masked-scatter write (single-buffer state)
// ---------------------------------------------------------------------------
__global__ __launch_bounds__(128)
void phase23(int step, int step0, float* __restrict__ out) {
    int r = blockIdx.x;
    int b = r >> 7, n = r & 127;
    int t = threadIdx.x;
    const int browbase = b * NSQ;
    const int sb = step * 8 + b;

    float4 acc = make_float4(0.f, 0.f, 0.f, 0.f);
    if (!step0) {
        const int cnt = g_cntD[sb * 128 + n];
        const int* lst = g_listD + ((size_t)sb * 128 + n) * 128;
        for (int k = 0; k < cnt; k++) {
            float4 v = ((const float4*)g_fc)[(size_t)(browbase + lst[k]) * 128 + t];
            acc.x += v.x; acc.y += v.y; acc.z += v.z; acc.w += v.w;
        }
    }
    float4 iu = ((const float4*)g_iu)[(size_t)r * 128 + t];
    float4 cf = make_float4(iu.x + acc.x, iu.y + acc.y,
                            iu.z + acc.z, iu.w + acc.w);
    float4 ov = ((const float4*)g_o)[(size_t)r * 128 + t];
    float4 hf;
    hf.x = ov.x * tanhf(cf.x);
    hf.y = ov.y * tanhf(cf.y);
    hf.z = ov.z * tanhf(cf.z);
    hf.w = ov.w * tanhf(cf.w);

    const int nm = g_nmask[step];
    if (r < nm) {
        const int q = g_dest[step * ROWS + r];
        if (out) {
            ((float4*)out)[(size_t)q * 128 + t] = hf;
        } else {
            ((float4*)g_h)[(size_t)q * 128 + t] = hf;
            ((float4*)g_c)[(size_t)q * 128 + t] = cf;
            float4 hr;
            hr.x = tf32r(hf.x); hr.y = tf32r(hf.y);
            hr.z = tf32r(hf.z); hr.w = tf32r(hf.w);
            ((float4*)g_hr)[(size_t)q * 128 + t] = hr;
        }
    }
    if (out && !g_maskv[step * ROWS + r]) {
        ((float4*)out)[(size_t)r * 128 + t] =
            ((const float4*)g_h)[(size_t)r * 128 + t];
    }
}

// ---------------------------------------------------------------------------
// Launch
// ---------------------------------------------------------------------------
extern "C" void kernel_launch(void* const* d_in, const int* in_sizes, int n_in,
                              void* d_out, int out_size) {
    const int*   ids      = (const int*)d_in[0];
    const int*   tree     = (const int*)d_in[1];
    const float* emb      = (const float*)d_in[2];
    const float* W_ioux   = (const float*)d_in[3];
    const float* W_iouh_r = (const float*)d_in[4];
    const float* b_iouh_r = (const float*)d_in[5];
    const float* W_iouh_l = (const float*)d_in[6];
    const float* b_iouh_l = (const float*)d_in[7];
    const float* W_fx     = (const float*)d_in[8];
    const float* W_fh0    = (const float*)d_in[9];
    const float* b_fh0    = (const float*)d_in[10];
    const float* W_fh1    = (const float*)d_in[11];
    const float* b_fh1    = (const float*)d_in[12];
    const float* W_fh2    = (const float*)d_in[13];
    const float* b_fh2    = (const float*)d_in[14];
    const float* W_fh3    = (const float*)d_in[15];
    const float* b_fh3    = (const float*)d_in[16];

    cudaFuncSetAttribute(gemm_mma, cudaFuncAttributeMaxDynamicSharedMemorySize,
                         SMEM_DYN);

    float *pX, *pWtPre, *pWtStep, *pB, *pG, *pHr;
    cudaGetSymbolAddress((void**)&pX,      g_x);
    cudaGetSymbolAddress((void**)&pWtPre,  g_Wt_pre);
    cudaGetSymbolAddress((void**)&pWtStep, g_Wt_step);
    cudaGetSymbolAddress((void**)&pB,      g_bstep);
    cudaGetSymbolAddress((void**)&pG,      g_G);
    cudaGetSymbolAddress((void**)&pHr,     g_hr);

    init_k<<<ROWS, 128>>>(ids, emb, b_iouh_r, b_iouh_l,
                          b_fh0, b_fh1, b_fh2, b_fh3);
    tr_all<<<dim3(16, 128), 256>>>(W_ioux, W_fx, W_iouh_r, W_iouh_l,
                                   W_fh0, W_fh1, W_fh2, W_fh3);
    lists_k<<<NSTEPS * NB, 128>>>(tree);
    ranks_k<<<NSTEPS, 1024>>>(tree);

    // precompute GEMM with fused activation-split epilogue
    gemm_mma<<<dim3(NW / 128, ROWS / 128), 256, SMEM_DYN>>>(pX, pWtPre,
                                                            nullptr, pG, 1);

    // step 0: h=0 (GEMM folded into bias counts), c=0 (fc==0)
    phase1<<<ROWS, 128>>>(tree, 0, 1);
    phase23<<<ROWS, 128>>>(0, 1, nullptr);

    for (int s = 1; s < NSTEPS; s++) {
        gemm_mma<<<dim3(NW / 128, ROWS / 128), 256, SMEM_DYN>>>(
            pHr, pWtStep, pB, pG, 0);
        phase1<<<ROWS, 128>>>(tree, s, 0);
        phase23<<<ROWS, 128>>>(s, 0,
                               (s == NSTEPS - 1) ? (float*)d_out : nullptr);
    }
}